// round 4
// baseline (speedup 1.0000x reference)
#include <cuda_runtime.h>
#include <math.h>

// ---------------------------------------------------------------------------
// FCOS3D target assignment — round 4: prologue elimination.
// vs R3: no payload staging (direct global gather of the winner only, yaw
// computed per point), analytic per-block bbox (no shuffle reduction), single
// __syncthreads, filter loads straight from global, 256-thread blocks.
// ---------------------------------------------------------------------------

#define NLVL 5
#define NPTS 30929
#define INF_ 1.0e8f
#define MAXM 128

__device__ __constant__ int   c_off[NLVL + 1] = {0, 23200, 29000, 30450, 30825, 30929};
__device__ __constant__ int   c_w[NLVL]       = {200, 100, 50, 25, 13};
__device__ __constant__ float c_s[NLVL]       = {8.f, 16.f, 32.f, 64.f, 128.f};
__device__ __constant__ float c_inv_s[NLVL]   = {0.125f, 0.0625f, 0.03125f, 0.015625f, 0.0078125f};
__device__ __constant__ float c_cent_k[NLVL]  = {
    -2.5f / (1.414f * 8.f   * 1.5f),
    -2.5f / (1.414f * 16.f  * 1.5f),
    -2.5f / (1.414f * 32.f  * 1.5f),
    -2.5f / (1.414f * 64.f  * 1.5f),
    -2.5f / (1.414f * 128.f * 1.5f)};
__device__ __constant__ float c_r0[NLVL]      = {-1.f, 48.f, 96.f, 192.f, 384.f};
__device__ __constant__ float c_r1[NLVL]      = {48.f, 96.f, 192.f, 384.f, 1.0e8f};

__global__ void __launch_bounds__(256)
fcos3d_target_kernel(
    const float* __restrict__ gt_bboxes,    // (B, M, 4)
    const float* __restrict__ g3d,          // (B, M, 9)
    const int*   __restrict__ gl3d,         // (B, M)
    const float* __restrict__ centers2d,    // (B, M, 2)
    const float* __restrict__ depths,       // (B, M)
    const int*   __restrict__ attrs,        // (B, M)
    float*       __restrict__ out,
    int M, int B)
{
    const int b    = blockIdx.y;
    const int tid  = threadIdx.x;
    const int lane = tid & 31;
    const int wid  = tid >> 5;

    __shared__ float4 s_cbb[MAXM];
    __shared__ float2 s_cc[MAXM];
    __shared__ int    s_cidx[MAXM];
    __shared__ int    s_ncand;

    // ---- per-thread point coords (clamped for convergence) ----
    const int n0    = blockIdx.x * blockDim.x;
    const int n_raw = n0 + tid;
    const bool valid = (n_raw < NPTS);
    const int n = valid ? n_raw : (NPTS - 1);

    int lvl = 0;
#pragma unroll
    for (int i = 1; i < NLVL; i++)
        if (n >= c_off[i]) lvl = i;

    const int   p   = n - c_off[lvl];
    const int   w   = c_w[lvl];
    const float s   = c_s[lvl];
    const float x   = (float)(p % w) * s + 0.5f * s;
    const float y   = (float)(p / w) * s + 0.5f * s;
    const float r0  = c_r0[lvl];
    const float r1  = c_r1[lvl];
    const float rad = s * 1.5f;

    // ---- warp 0: analytic block bbox + filter + ordered compaction ----
    if (wid == 0) {
        const int nlast = min(n0 + (int)blockDim.x - 1, NPTS - 1);
        float bxmin = 1e30f, bxmax = -1e30f;
        float bymin = 1e30f, bymax = -1e30f, rmx = 0.f;
#pragma unroll
        for (int l = 0; l < NLVL; l++) {
            const int a = max(n0, c_off[l]);
            const int e = min(nlast, c_off[l + 1] - 1);
            if (a > e) continue;
            const int   pw = c_w[l];
            const float ls = c_s[l];
            const int p0 = a - c_off[l], p1 = e - c_off[l];
            const int row0 = p0 / pw, row1 = p1 / pw;
            const int xlo = (row1 > row0) ? 0 : (p0 % pw);
            const int xhi = (row1 > row0) ? (pw - 1) : (p1 % pw);
            bxmin = fminf(bxmin, (float)xlo * ls + 0.5f * ls);
            bxmax = fmaxf(bxmax, (float)xhi * ls + 0.5f * ls);
            bymin = fminf(bymin, (float)row0 * ls + 0.5f * ls);
            bymax = fmaxf(bymax, (float)row1 * ls + 0.5f * ls);
            rmx   = fmaxf(rmx, 1.5f * ls);
        }
        bxmin -= rmx; bxmax += rmx; bymin -= rmx; bymax += rmx;

        const float2* cptr = reinterpret_cast<const float2*>(centers2d) + (size_t)b * M;
        const float4* bptr = reinterpret_cast<const float4*>(gt_bboxes) + (size_t)b * M;
        int cnt = 0;
        for (int m0 = 0; m0 < M; m0 += 32) {
            const int m = m0 + lane;
            bool ok = false;
            float2 c = make_float2(0.f, 0.f);
            if (m < M) {
                c  = cptr[m];
                ok = (c.x >= bxmin) & (c.x <= bxmax) &
                     (c.y >= bymin) & (c.y <= bymax);
            }
            const unsigned mask = __ballot_sync(0xffffffffu, ok);
            if (ok) {
                const int pos = cnt + __popc(mask & ((1u << lane) - 1u));
                s_cbb[pos]  = bptr[m];
                s_cc[pos]   = c;
                s_cidx[pos] = m;
            }
            cnt += __popc(mask);
        }
        if (lane == 0) s_ncand = cnt;
    }
    __syncthreads();

    if (!valid) return;

    // ---- argmin over candidates (squared distance; first-min tie-break) ----
    const int ncand = s_ncand;
    float best = INF_;
    int   bk   = -1;
    for (int k = 0; k < ncand; k++) {
        const float4 bb = s_cbb[k];
        const float2 c  = s_cc[k];
        const float dx = x - c.x;
        const float dy = y - c.y;
        const float left   = x - bb.x;
        const float top    = y - bb.y;
        const float right  = bb.z - x;
        const float bottom = bb.w - y;
        const float mrd = fmaxf(fmaxf(left, top), fmaxf(right, bottom));
        const bool ok = (mrd >= r0) & (mrd <= r1) &
                        (fmaxf(fabsf(dx), fabsf(dy)) < rad);
        const float d2 = ok ? fmaf(dx, dx, dy * dy) : INF_;
        if (d2 < best) { best = d2; bk = k; }
    }

    const bool bg = (best >= INF_);
    const int  bi = (bk >= 0) ? s_cidx[bk] : 0;   // all-INF argmin -> index 0

    // ---- direct gather of the winner's payload (L1/L2 resident) ----
    const int gi = b * M + bi;
    const float2 c = reinterpret_cast<const float2*>(centers2d)[gi];
    const float dx = x - c.x;
    const float dy = y - c.y;
    const float* g = g3d + (size_t)gi * 9;
    const float g0 = g[0], g2 = g[2], g6 = g[6];
    const float yaw = -atan2f(g0, g2) + g6;

    const float cent = expf(c_cent_k[lvl] * sqrtf(fmaf(dx, dx, dy * dy)));

    const int BN   = B * NPTS;
    const int npl  = c_off[lvl + 1] - c_off[lvl];
    const int base = c_off[lvl] * B + b * npl + p;
    const float inv_s = c_inv_s[lvl];

    out[base]           = bg ? 10.f : (float)gl3d[gi];   // labels_3d
    out[10 * BN + base] = cent;                          // centerness
    out[11 * BN + base] = bg ? 9.f : (float)attrs[gi];   // attr

    float* bo = out + BN + (size_t)base * 9;             // bbox_targets_3d
    bo[0] = dx * inv_s;
    bo[1] = dy * inv_s;
    bo[2] = depths[gi];
    bo[3] = g[3];
    bo[4] = g[4];
    bo[5] = g[5];
    bo[6] = yaw;
    bo[7] = g[7];
    bo[8] = g[8];
}

extern "C" void kernel_launch(void* const* d_in, const int* in_sizes, int n_in,
                              void* d_out, int out_size)
{
    const float* gt_bboxes = (const float*)d_in[0];
    const float* g3d       = (const float*)d_in[2];
    const int*   gl3d      = (const int*)  d_in[3];
    const float* centers2d = (const float*)d_in[4];
    const float* depths    = (const float*)d_in[5];
    const int*   attrs     = (const int*)  d_in[6];
    float* out = (float*)d_out;

    const int B = out_size / (12 * NPTS);
    const int M = in_sizes[1] / B;

    const int threads = 256;
    dim3 grid((NPTS + threads - 1) / threads, B);
    fcos3d_target_kernel<<<grid, threads>>>(
        gt_bboxes, g3d, gl3d, centers2d, depths, attrs, out, M, B);
}